// round 9
// baseline (speedup 1.0000x reference)
#include <cuda_runtime.h>

// out[j]     = dot(X[r1(j)], p), r1(j) = inds1[2j]*28 + inds1[2j+1], j in [0,100)
// out[100+j] = dot(Y[r2(j)], p)
// Pair dot j (X) with dot j+100 (Y) in one block: the 8 p-float4 per thread are
// loaded ONCE and reused for both rows -> L2 p-traffic halves (51MB -> 39MB).
// 100 blocks x 1024 threads, direct writes, no atomics/partials/tails.

#define Q      32768
#define QV     (Q / 4)      // 8192 float4 per row
#define NT     1024
#define W_DIM  28

__device__ __forceinline__ float dot4(float4 a, float4 b) {
    return a.x * b.x + a.y * b.y + a.z * b.z + a.w * b.w;
}

__global__ __launch_bounds__(NT, 1)
void paired_dot_kernel(const float* __restrict__ X,
                       const float* __restrict__ Y,
                       const float* __restrict__ p,
                       const int*   __restrict__ inds1,
                       const int*   __restrict__ inds2,
                       float* __restrict__ out)
{
    const int j = blockIdx.x;            // 0..99

    // Row indices first (longest dependency chain: inds -> row loads).
    const int r1 = inds1[2 * j] * W_DIM + inds1[2 * j + 1];
    const int r2 = inds2[2 * j] * W_DIM + inds2[2 * j + 1];

    const float4* __restrict__ pv   = reinterpret_cast<const float4*>(p);
    const float4* __restrict__ rowX = reinterpret_cast<const float4*>(X + (size_t)r1 * Q);
    const float4* __restrict__ rowY = reinterpret_cast<const float4*>(Y + (size_t)r2 * Q);

    const int i0 = threadIdx.x;

    // p loads: once, reused for both rows.
    float4 p0 = pv[i0];
    float4 p1 = pv[i0 +     NT];
    float4 p2 = pv[i0 + 2 * NT];
    float4 p3 = pv[i0 + 3 * NT];
    float4 p4 = pv[i0 + 4 * NT];
    float4 p5 = pv[i0 + 5 * NT];
    float4 p6 = pv[i0 + 6 * NT];
    float4 p7 = pv[i0 + 7 * NT];

    // X row: 8 independent LDG.128.
    float4 x0 = rowX[i0];
    float4 x1 = rowX[i0 +     NT];
    float4 x2 = rowX[i0 + 2 * NT];
    float4 x3 = rowX[i0 + 3 * NT];
    float4 x4 = rowX[i0 + 4 * NT];
    float4 x5 = rowX[i0 + 5 * NT];
    float4 x6 = rowX[i0 + 6 * NT];
    float4 x7 = rowX[i0 + 7 * NT];

    float sumX = dot4(x0, p0);
    sumX += dot4(x1, p1);
    sumX += dot4(x2, p2);
    sumX += dot4(x3, p3);
    sumX += dot4(x4, p4);
    sumX += dot4(x5, p5);
    sumX += dot4(x6, p6);
    sumX += dot4(x7, p7);

    // Y row: reuses the x registers (issued after X consumed).
    float4 y0 = rowY[i0];
    float4 y1 = rowY[i0 +     NT];
    float4 y2 = rowY[i0 + 2 * NT];
    float4 y3 = rowY[i0 + 3 * NT];
    float4 y4 = rowY[i0 + 4 * NT];
    float4 y5 = rowY[i0 + 5 * NT];
    float4 y6 = rowY[i0 + 6 * NT];
    float4 y7 = rowY[i0 + 7 * NT];

    float sumY = dot4(y0, p0);
    sumY += dot4(y1, p1);
    sumY += dot4(y2, p2);
    sumY += dot4(y3, p3);
    sumY += dot4(y4, p4);
    sumY += dot4(y5, p5);
    sumY += dot4(y6, p6);
    sumY += dot4(y7, p7);

    // warp reduce both sums
    #pragma unroll
    for (int off = 16; off > 0; off >>= 1) {
        sumX += __shfl_xor_sync(0xFFFFFFFFu, sumX, off);
        sumY += __shfl_xor_sync(0xFFFFFFFFu, sumY, off);
    }

    __shared__ float warp_sums[NT / 32][2];
    const int lane = threadIdx.x & 31;
    const int wid  = threadIdx.x >> 5;
    if (lane == 0) {
        warp_sums[wid][0] = sumX;
        warp_sums[wid][1] = sumY;
    }
    __syncthreads();

    if (wid == 0) {
        float sx = (lane < NT / 32) ? warp_sums[lane][0] : 0.0f;
        float sy = (lane < NT / 32) ? warp_sums[lane][1] : 0.0f;
        #pragma unroll
        for (int off = 16; off > 0; off >>= 1) {
            sx += __shfl_xor_sync(0xFFFFFFFFu, sx, off);
            sy += __shfl_xor_sync(0xFFFFFFFFu, sy, off);
        }
        if (lane == 0) {
            out[j]       = sx;
            out[j + 100] = sy;
        }
    }
}

extern "C" void kernel_launch(void* const* d_in, const int* in_sizes, int n_in,
                              void* d_out, int out_size)
{
    const float* X   = (const float*)d_in[0];
    const float* Y   = (const float*)d_in[1];
    const float* p   = (const float*)d_in[2];
    const int* inds1 = (const int*)d_in[3];
    const int* inds2 = (const int*)d_in[4];
    float* out       = (float*)d_out;

    paired_dot_kernel<<<100, NT>>>(X, Y, p, inds1, inds2, out);
}